// round 1
// baseline (speedup 1.0000x reference)
#include <cuda_runtime.h>
#include <cstdint>

// LIF spike scan over T=8 (innermost, contiguous axis).
// x: [B=32, C=128, H=32, W=32, T=8] fp32 -> out: same shape, fp32 spikes {0,1}.
// Recurrence per spatial position p:
//   u = TAU * u_prev * (1 - o_prev) + x[p][t];  o = (u > VTH) ? 1 : 0
// Each thread owns one position: load 2x float4, scan in registers, store 2x float4.

#define TAU 0.2f
#define VTH 0.3f

__global__ void __launch_bounds__(256, 8)
lif_spike_kernel(const float* __restrict__ x, float* __restrict__ out, int n_pos) {
    int p = blockIdx.x * blockDim.x + threadIdx.x;
    if (p >= n_pos) return;

    const float4* __restrict__ x4 = reinterpret_cast<const float4*>(x) + (size_t)p * 2;
    float4* __restrict__ o4 = reinterpret_cast<float4*>(out) + (size_t)p * 2;

    float4 a = x4[0];
    float4 b = x4[1];

    float xin[8] = {a.x, a.y, a.z, a.w, b.x, b.y, b.z, b.w};
    float spk[8];

    float u = 0.0f;
    float o = 0.0f;
#pragma unroll
    for (int t = 0; t < 8; t++) {
        u = TAU * u * (1.0f - o) + xin[t];
        o = (u - VTH > 0.0f) ? 1.0f : 0.0f;
        spk[t] = o;
    }

    float4 r0 = make_float4(spk[0], spk[1], spk[2], spk[3]);
    float4 r1 = make_float4(spk[4], spk[5], spk[6], spk[7]);
    o4[0] = r0;
    o4[1] = r1;
}

extern "C" void kernel_launch(void* const* d_in, const int* in_sizes, int n_in,
                              void* d_out, int out_size) {
    const float* x = (const float*)d_in[0];
    float* out = (float*)d_out;
    int n_total = in_sizes[0];     // B*C*H*W*T
    int n_pos = n_total / 8;       // positions, each owning T=8 floats

    int threads = 256;
    int blocks = (n_pos + threads - 1) / threads;
    lif_spike_kernel<<<blocks, threads>>>(x, out, n_pos);
}

// round 2
// speedup vs baseline: 1.0316x; 1.0316x over previous
#include <cuda_runtime.h>
#include <cstdint>

// LIF spike scan over T=8 (innermost, contiguous axis).
// x: [32,128,32,32,8] fp32 -> out same shape, spikes {0,1} fp32.
// Pure streaming kernel: 1 thread = 1 spatial position = 32B in, 32B out.
// sm_103a: use 256-bit global ld/st (one LDG.E.256 + one STG.E.256 per thread).

#define TAU 0.2f
#define VTH 0.3f

__global__ void __launch_bounds__(256, 8)
lif_spike_kernel(const float* __restrict__ x, float* __restrict__ out, int n_pos) {
    int p = blockIdx.x * blockDim.x + threadIdx.x;
    if (p >= n_pos) return;

    const float* xp = x + (size_t)p * 8;
    float* op = out + (size_t)p * 8;

    float x0, x1, x2, x3, x4, x5, x6, x7;
    // 256-bit read-once load (sm_100+), bypasses L1 persistence (.nc not needed; use .cs evict-first)
    asm volatile(
        "ld.global.cs.v8.f32 {%0,%1,%2,%3,%4,%5,%6,%7}, [%8];"
        : "=f"(x0), "=f"(x1), "=f"(x2), "=f"(x3),
          "=f"(x4), "=f"(x5), "=f"(x6), "=f"(x7)
        : "l"(xp));

    float u = 0.0f;
    float o = 0.0f;
    float s0, s1, s2, s3, s4, s5, s6, s7;

    u = x0;                              // TAU*0*(1-0) + x0
    o = (u > VTH) ? 1.0f : 0.0f;  s0 = o;
    u = TAU * u * (1.0f - o) + x1;
    o = (u > VTH) ? 1.0f : 0.0f;  s1 = o;
    u = TAU * u * (1.0f - o) + x2;
    o = (u > VTH) ? 1.0f : 0.0f;  s2 = o;
    u = TAU * u * (1.0f - o) + x3;
    o = (u > VTH) ? 1.0f : 0.0f;  s3 = o;
    u = TAU * u * (1.0f - o) + x4;
    o = (u > VTH) ? 1.0f : 0.0f;  s4 = o;
    u = TAU * u * (1.0f - o) + x5;
    o = (u > VTH) ? 1.0f : 0.0f;  s5 = o;
    u = TAU * u * (1.0f - o) + x6;
    o = (u > VTH) ? 1.0f : 0.0f;  s6 = o;
    u = TAU * u * (1.0f - o) + x7;
    o = (u > VTH) ? 1.0f : 0.0f;  s7 = o;

    // 256-bit streaming store (evict-first: write stream barely fits L2, don't thrash it)
    asm volatile(
        "st.global.cs.v8.f32 [%0], {%1,%2,%3,%4,%5,%6,%7,%8};"
        :
        : "l"(op),
          "f"(s0), "f"(s1), "f"(s2), "f"(s3),
          "f"(s4), "f"(s5), "f"(s6), "f"(s7)
        : "memory");
}

extern "C" void kernel_launch(void* const* d_in, const int* in_sizes, int n_in,
                              void* d_out, int out_size) {
    const float* x = (const float*)d_in[0];
    float* out = (float*)d_out;
    int n_total = in_sizes[0];   // B*C*H*W*T
    int n_pos = n_total / 8;     // one position per thread

    int threads = 256;
    int blocks = (n_pos + threads - 1) / threads;
    lif_spike_kernel<<<blocks, threads>>>(x, out, n_pos);
}